// round 4
// baseline (speedup 1.0000x reference)
#include <cuda_runtime.h>
#include <cstdint>

#define K  11
#define TT 512
#define BB 4096
#define IMPOSSIBLE_F (-10000.0f)

// Precomputed constant tables (written by setup kernel each launch; deterministic).
__device__ float g_transM[K * K];   // masked transitions (log domain, for score)
__device__ float g_expT[K * K];     // exp(masked transitions) (for alpha recursion)
__device__ float g_startM[K];       // masked start transitions
__device__ float g_endM[K];         // end transitions (no constraint)
__device__ int   g_u8mode;          // 1 if mask buffer is 1-byte bool, 0 if 4-byte

__global__ void setup_kernel(const float* __restrict__ trans,
                             const float* __restrict__ startv,
                             const float* __restrict__ endv,
                             const void*  __restrict__ maskp,
                             float* __restrict__ out) {
    int t = threadIdx.x;
    if (t < K * K) {
        int i = t / K, j = t % K;
        // BIO constraints: into O (j==0) always allowed; into B (j odd) always
        // allowed; into I_i (j even >=2) only from B_i (i==j-1) or I_i (i==j).
        bool allowed = (j == 0) || (j & 1) || (i == j - 1) || (i == j);
        float v = allowed ? trans[t] : IMPOSSIBLE_F;
        g_transM[t] = v;
        g_expT[t]   = expf(v);   // exp(-10000) underflows to exactly 0 -> forbidden
    }
    if (t < K) {
        bool sforb = (t >= 2) && ((t & 1) == 0);   // cannot start with I_i
        g_startM[t] = sforb ? IMPOSSIBLE_F : startv[t];
        g_endM[t]   = endv[t];
    }
    if (t == 0) {
        // Lengths >= 256, so mask[0][1] is true. Byte[1]!=0 iff 1-byte bool.
        const unsigned char* mb = (const unsigned char*)maskp;
        g_u8mode = (mb[1] != 0) ? 1 : 0;
        out[0] = 0.0f;
    }
}

// 4-lane groups, 8 batch rows per warp, 1 warp per block (512 blocks).
// Lane l owns tag-states [3l, 3l+2] (lane 3: states 9,10 + zero dummy).
// Unnormalized exp-domain state rho; renorm by state-0 every 8-step chunk.
__global__ void __launch_bounds__(32)
crf_kernel(const float* __restrict__ em,
           const void*  __restrict__ maskp,
           const int*   __restrict__ tags,
           float* __restrict__ out) {
    __shared__ float sh_trans[K * K];
    for (int i = threadIdx.x; i < K * K; i += 32) sh_trans[i] = g_transM[i];
    __syncwarp();

    const int tid  = threadIdx.x;
    const int lane = tid & 3;
    const int grp  = tid >> 2;
    const int b    = blockIdx.x * 8 + grp;
    const unsigned gmask = 0xFu << (tid & 28);

    const int s0 = 3 * lane;
    const int s1 = 3 * lane + 1;
    const bool v2 = (3 * lane + 2) < K;
    const int s2 = v2 ? (3 * lane + 2) : (K - 1);   // clamped for safe loads

    // Per-lane columns of expT (zeros for the dummy state keep rho2 == 0).
    float eT0[K], eT1[K], eT2[K];
#pragma unroll
    for (int i = 0; i < K; i++) {
        eT0[i] = g_expT[i * K + s0];
        eT1[i] = g_expT[i * K + s1];
        eT2[i] = v2 ? g_expT[i * K + s2] : 0.0f;
    }
    const float expE0 = __expf(g_endM[s0]);
    const float expE1 = __expf(g_endM[s1]);
    const float expE2 = v2 ? __expf(g_endM[s2]) : 0.0f;

    // Sequence length = popcount of prefix mask row (vectorized).
    unsigned lenu = 0u;
    if (g_u8mode) {
        const uint4* m4 = (const uint4*)((const unsigned char*)maskp + (size_t)b * TT);
#pragma unroll
        for (int i = lane; i < TT / 16; i += 4) {
            uint4 x = m4[i];
            lenu = __dp4a(x.x, 0x01010101u, lenu);
            lenu = __dp4a(x.y, 0x01010101u, lenu);
            lenu = __dp4a(x.z, 0x01010101u, lenu);
            lenu = __dp4a(x.w, 0x01010101u, lenu);
        }
    } else {
        const uint4* m4 = (const uint4*)((const unsigned*)maskp + (size_t)b * TT);
        for (int i = lane; i < TT / 4; i += 4) {
            uint4 x = m4[i];
            lenu += (x.x != 0u) + (x.y != 0u) + (x.z != 0u) + (x.w != 0u);
        }
    }
    int len = (int)lenu;
    len += __shfl_xor_sync(gmask, len, 1, 4);
    len += __shfl_xor_sync(gmask, len, 2, 4);

    const float* erow = em   + (size_t)b * TT * K;
    const int*   trow = tags + (size_t)b * TT;

    // ---- t = 0 ----
    float e0a = erow[s0], e0b = erow[s1], e0c = erow[s2];
    float a0l = g_startM[s0] + e0a;
    float a1l = g_startM[s1] + e0b;
    float a2l = v2 ? (g_startM[s2] + e0c) : -1e30f;
    float aO  = __shfl_sync(gmask, a0l, 0, 4);       // alpha[O] (state 0, lane 0)
    float rho0 = __expf(a0l - aO);
    float rho1 = __expf(a1l - aO);
    float rho2 = __expf(a2l - aO);
    float A0 = aO;

    int   ptag     = trow[0];
    float transacc = g_startM[ptag];                 // uniform within group
    float emacc    = 0.0f;                           // owner-lane accumulation
    if      (ptag == s0)        emacc = e0a;
    else if (ptag == s1)        emacc = e0b;
    else if (v2 && ptag == s2)  emacc = e0c;

    // Double-buffered 8-step queues.
    float E0A[8], E1A[8], E2A[8], E0B[8], E1B[8], E2B[8];
    int   TGA[8], TGB[8];

#define LOAD_CHUNK(E0Q, E1Q, E2Q, TGQ, TB)                                   \
    {                                                                        \
        _Pragma("unroll")                                                    \
        for (int k_ = 0; k_ < 8; k_++) {                                     \
            int tt_ = (TB) + k_;                                             \
            tt_ = (tt_ < TT) ? tt_ : (TT - 1);                               \
            const float* ep_ = erow + (size_t)tt_ * K;                       \
            E0Q[k_] = ep_[s0]; E1Q[k_] = ep_[s1]; E2Q[k_] = ep_[s2];         \
            TGQ[k_] = trow[tt_];                                             \
        }                                                                    \
    }

#define STEP_CORE(EC0, EC1, EC2, TG, VALID)                                  \
    {                                                                        \
        float r_[K];                                                         \
        r_[0]  = __shfl_sync(gmask, rho0, 0, 4);                             \
        r_[1]  = __shfl_sync(gmask, rho1, 0, 4);                             \
        r_[2]  = __shfl_sync(gmask, rho2, 0, 4);                             \
        r_[3]  = __shfl_sync(gmask, rho0, 1, 4);                             \
        r_[4]  = __shfl_sync(gmask, rho1, 1, 4);                             \
        r_[5]  = __shfl_sync(gmask, rho2, 1, 4);                             \
        r_[6]  = __shfl_sync(gmask, rho0, 2, 4);                             \
        r_[7]  = __shfl_sync(gmask, rho1, 2, 4);                             \
        r_[8]  = __shfl_sync(gmask, rho2, 2, 4);                             \
        r_[9]  = __shfl_sync(gmask, rho0, 3, 4);                             \
        r_[10] = __shfl_sync(gmask, rho1, 3, 4);                             \
        float sa0 = 0.f, sa1 = 0.f, sb0 = 0.f, sb1 = 0.f, sc0 = 0.f, sc1 = 0.f; \
        _Pragma("unroll")                                                    \
        for (int i_ = 0; i_ < K; i_++) {                                     \
            if (i_ & 1) { sa1 = fmaf(r_[i_], eT0[i_], sa1);                  \
                          sb1 = fmaf(r_[i_], eT1[i_], sb1);                  \
                          sc1 = fmaf(r_[i_], eT2[i_], sc1); }                \
            else        { sa0 = fmaf(r_[i_], eT0[i_], sa0);                  \
                          sb0 = fmaf(r_[i_], eT1[i_], sb0);                  \
                          sc0 = fmaf(r_[i_], eT2[i_], sc0); }                \
        }                                                                    \
        float pe0_ = __expf(EC0), pe1_ = __expf(EC1), pe2_ = __expf(EC2);    \
        if (VALID) {                                                         \
            rho0 = (sa0 + sa1) * pe0_;                                       \
            rho1 = (sb0 + sb1) * pe1_;                                       \
            rho2 = (sc0 + sc1) * pe2_;                                       \
            int tg_ = (TG);                                                  \
            transacc += sh_trans[ptag * K + tg_];                            \
            if      (tg_ == s0)       emacc += (EC0);                        \
            else if (tg_ == s1)       emacc += (EC1);                        \
            else if (v2 && tg_ == s2) emacc += (EC2);                        \
            ptag = tg_;                                                      \
        }                                                                    \
    }

#define CHUNK_FULL(E0Q, E1Q, E2Q, TGQ)                                       \
    {                                                                        \
        _Pragma("unroll")                                                    \
        for (int kc_ = 0; kc_ < 8; kc_++)                                    \
            STEP_CORE(E0Q[kc_], E1Q[kc_], E2Q[kc_], TGQ[kc_], true)          \
        float m_ = __shfl_sync(gmask, rho0, 0, 4);                           \
        float inv_ = __frcp_rn(m_);                                          \
        rho0 *= inv_; rho1 *= inv_; rho2 *= inv_;                            \
        A0 += __logf(m_);                                                    \
    }

#define CHUNK_MASKED(E0Q, E1Q, E2Q, TGQ, TB)                                 \
    {                                                                        \
        _Pragma("unroll")                                                    \
        for (int kc_ = 0; kc_ < 8; kc_++)                                    \
            STEP_CORE(E0Q[kc_], E1Q[kc_], E2Q[kc_], TGQ[kc_],                \
                      ((TB) + kc_ < len))                                    \
    }

    int t = 1;
    LOAD_CHUNK(E0A, E1A, E2A, TGA, t);
    bool useA = true;
    while (t + 8 <= len) {
        if (useA) { LOAD_CHUNK(E0B, E1B, E2B, TGB, t + 8);
                    CHUNK_FULL(E0A, E1A, E2A, TGA); }
        else      { LOAD_CHUNK(E0A, E1A, E2A, TGA, t + 8);
                    CHUNK_FULL(E0B, E1B, E2B, TGB); }
        useA = !useA;
        t += 8;
    }
    if (t < len) {   // tail (<8 steps), data already prefetched in current buffer
        if (useA) { CHUNK_MASKED(E0A, E1A, E2A, TGA, t) }
        else      { CHUNK_MASKED(E0B, E1B, E2B, TGB, t) }
    }

    // z = A0 + log( sum_s rho_s * exp(end_s) )  (<= 15 un-renormed steps, safe)
    float v = rho0 * expE0 + rho1 * expE1 + rho2 * expE2;
    v += __shfl_xor_sync(gmask, v, 1, 4);
    v += __shfl_xor_sync(gmask, v, 2, 4);
    float z = A0 + __logf(v);

    float ems = emacc;
    ems += __shfl_xor_sync(gmask, ems, 1, 4);
    ems += __shfl_xor_sync(gmask, ems, 2, 4);

    if (lane == 0) {
        float score = transacc + ems + g_endM[ptag];
        atomicAdd(out, (score - z) * (1.0f / (float)BB));
    }
}

extern "C" void kernel_launch(void* const* d_in, const int* in_sizes, int n_in,
                              void* d_out, int out_size) {
    const float* em     = (const float*)d_in[0];
    const void*  maskp  = d_in[1];
    const int*   tags   = (const int*)d_in[2];
    const float* trans  = (const float*)d_in[3];
    const float* startv = (const float*)d_in[4];
    const float* endv   = (const float*)d_in[5];
    float* out = (float*)d_out;

    setup_kernel<<<1, 128>>>(trans, startv, endv, maskp, out);
    crf_kernel<<<BB / 8, 32>>>(em, maskp, tags, out);
}

// round 5
// speedup vs baseline: 1.0466x; 1.0466x over previous
#include <cuda_runtime.h>
#include <cstdint>

#define K  11
#define TT 512
#define BB 4096
#define NCHUNK (TT / 4)          // 128 chunks of 4 steps
#define IMPOSSIBLE_F (-10000.0f)

// Precomputed tables (written by setup kernel each launch; deterministic).
__device__ float g_transM[K * K];  // masked transitions (log domain, for score)
__device__ float g_A[K];           // exp(trans[i][0])        (-> O, all allowed)
__device__ float g_C[5];           // exp(trans[0][1+2j])     (O -> B_j)
__device__ float g_D[5];           // exp(trans[1+2j][2+2j])  (B_j -> I_j)
__device__ float g_F[5];           // exp(trans[2+2j][2+2j])  (I_j -> I_j)
__device__ float g_startM[K];
__device__ float g_endM[K];
__device__ int   g_u8mode;

__global__ void setup_kernel(const float* __restrict__ trans,
                             const float* __restrict__ startv,
                             const float* __restrict__ endv,
                             const void*  __restrict__ maskp,
                             float* __restrict__ out) {
    int t = threadIdx.x;
    if (t < K * K) {
        int i = t / K, j = t % K;
        bool allowed = (j == 0) || (j & 1) || (i == j - 1) || (i == j);
        g_transM[t] = allowed ? trans[t] : IMPOSSIBLE_F;
    }
    if (t < K) {
        g_A[t] = expf(trans[t * K]);           // into O: always allowed
        bool sforb = (t >= 2) && !(t & 1);     // cannot start with I_i
        g_startM[t] = sforb ? IMPOSSIBLE_F : startv[t];
        g_endM[t]   = endv[t];
    }
    if (t < 5) {
        int bj = 1 + 2 * t, ij = 2 + 2 * t;
        g_C[t] = expf(trans[0 * K + bj]);
        g_D[t] = expf(trans[bj * K + ij]);
        g_F[t] = expf(trans[ij * K + ij]);
    }
    if (t == 0) {
        // lengths >= 256 so mask[0][1] true; byte[1]!=0 iff 1-byte bool buffer
        g_u8mode = (((const unsigned char*)maskp)[1] != 0) ? 1 : 0;
        out[0] = 0.0f;
    }
}

// Extract float #N (compile-time) from a float4[11] chunk window.
#define GETF(Q, N) (((N) & 3) == 0 ? Q[(N) >> 2].x : ((N) & 3) == 1 ? Q[(N) >> 2].y \
                  : ((N) & 3) == 2 ? Q[(N) >> 2].z : Q[(N) >> 2].w)
#define GETI(TQ, KK) ((KK) == 0 ? (TQ).x : (KK) == 1 ? (TQ).y : (KK) == 2 ? (TQ).z : (TQ).w)

// Select e[tg] from step registers via SEL tree (ALU pipe; avoids gather LDG).
#define PICK(TG) ((TG) < 4 ? ((TG) < 2 ? ((TG) == 0 ? e0_ : e1_)                    \
                                       : ((TG) == 2 ? e2_ : e3_))                   \
                 : ((TG) < 8 ? ((TG) < 6 ? ((TG) == 4 ? e4_ : e5_)                  \
                                         : ((TG) == 6 ? e6_ : e7_))                 \
                             : ((TG) < 10 ? ((TG) == 8 ? e8_ : e9_) : e10_)))

#define LOADC(Q, TQ, CI)                                                     \
    {                                                                        \
        int c_ = (CI); c_ = (c_ < NCHUNK) ? c_ : (NCHUNK - 1);               \
        const float4* p_ = e4 + c_ * 11;                                     \
        _Pragma("unroll") for (int q_ = 0; q_ < 11; q_++) Q[q_] = p_[q_];    \
        TQ = *(const int4*)(trow + c_ * 4);                                  \
    }

// One CRF step. Sparse BIO matvec in registers; SEL-freeze past len.
#define STEP(Q, TQ, T0, KK)                                                  \
    {                                                                        \
        const int t_ = (T0) + (KK);                                          \
        float e0_ = GETF(Q, (KK)*11 + 0),  e1_ = GETF(Q, (KK)*11 + 1);       \
        float e2_ = GETF(Q, (KK)*11 + 2),  e3_ = GETF(Q, (KK)*11 + 3);       \
        float e4_ = GETF(Q, (KK)*11 + 4),  e5_ = GETF(Q, (KK)*11 + 5);       \
        float e6_ = GETF(Q, (KK)*11 + 6),  e7_ = GETF(Q, (KK)*11 + 7);       \
        float e8_ = GETF(Q, (KK)*11 + 8),  e9_ = GETF(Q, (KK)*11 + 9);       \
        float e10_ = GETF(Q, (KK)*11 + 10);                                  \
        float p0_ = __expf(e0_), p1_ = __expf(e1_), p2_ = __expf(e2_);       \
        float p3_ = __expf(e3_), p4_ = __expf(e4_), p5_ = __expf(e5_);       \
        float p6_ = __expf(e6_), p7_ = __expf(e7_), p8_ = __expf(e8_);       \
        float p9_ = __expf(e9_), p10_ = __expf(e10_);                        \
        float ch0_ = r0 * cA0;                                               \
        float ch1_ = r1 * cA1;                                               \
        ch0_ = fmaf(r2, cA2, ch0_);   ch1_ = fmaf(r3, cA3, ch1_);            \
        ch0_ = fmaf(r4, cA4, ch0_);   ch1_ = fmaf(r5, cA5, ch1_);            \
        ch0_ = fmaf(r6, cA6, ch0_);   ch1_ = fmaf(r7, cA7, ch1_);            \
        ch0_ = fmaf(r8, cA8, ch0_);   ch1_ = fmaf(r9, cA9, ch1_);            \
        ch0_ = fmaf(r10, cA10, ch0_);                                        \
        float n0_  = (ch0_ + ch1_) * p0_;                                    \
        float n1_  = (r0 * cC0) * p1_;                                       \
        float n3_  = (r0 * cC1) * p3_;                                       \
        float n5_  = (r0 * cC2) * p5_;                                       \
        float n7_  = (r0 * cC3) * p7_;                                       \
        float n9_  = (r0 * cC4) * p9_;                                       \
        float n2_  = fmaf(r1, cD0, r2  * cF0) * p2_;                         \
        float n4_  = fmaf(r3, cD1, r4  * cF1) * p4_;                         \
        float n6_  = fmaf(r5, cD2, r6  * cF2) * p6_;                         \
        float n8_  = fmaf(r7, cD3, r8  * cF3) * p8_;                         \
        float n10_ = fmaf(r9, cD4, r10 * cF4) * p10_;                        \
        const bool vl_ = (t_ < len);                                         \
        r0 = vl_ ? n0_ : r0;   r1 = vl_ ? n1_ : r1;   r2 = vl_ ? n2_ : r2;   \
        r3 = vl_ ? n3_ : r3;   r4 = vl_ ? n4_ : r4;   r5 = vl_ ? n5_ : r5;   \
        r6 = vl_ ? n6_ : r6;   r7 = vl_ ? n7_ : r7;   r8 = vl_ ? n8_ : r8;   \
        r9 = vl_ ? n9_ : r9;   r10 = vl_ ? n10_ : r10;                       \
        int tg_ = GETI(TQ, KK);                                              \
        if (vl_) {                                                           \
            score += sh_trans[ptag * K + tg_] + PICK(tg_);                   \
            ptag = tg_;                                                      \
        }                                                                    \
    }

// Chunk renorm by state O. Invariant A0 + log(rho * x) preserved, so it is
// harmless for frozen lanes too.
#define RENORM                                                               \
    {                                                                        \
        float m_ = r0; float i_ = __frcp_rn(m_);                             \
        r0 = 1.0f;                                                           \
        r1 *= i_; r2 *= i_; r3 *= i_; r4 *= i_; r5 *= i_;                    \
        r6 *= i_; r7 *= i_; r8 *= i_; r9 *= i_; r10 *= i_;                   \
        A0 += __logf(m_);                                                    \
    }

#define PROC(Q, TQ, CI)                                                      \
    {                                                                        \
        const int tb_ = (CI) * 4;                                            \
        STEP(Q, TQ, tb_, 0) STEP(Q, TQ, tb_, 1)                              \
        STEP(Q, TQ, tb_, 2) STEP(Q, TQ, tb_, 3)                              \
        RENORM                                                               \
    }

// One batch row per thread: no shuffles, no smem on the recurrence.
__global__ void __launch_bounds__(32, 1)
crf_kernel(const float* __restrict__ em,
           const void*  __restrict__ maskp,
           const int*   __restrict__ tags,
           float* __restrict__ out) {
    __shared__ float sh_trans[K * K];
    __shared__ float sh_start[K];
    __shared__ float sh_end[K];
    {
        int tix = threadIdx.x;
        for (int i = tix; i < K * K; i += 32) sh_trans[i] = g_transM[i];
        if (tix < K) { sh_start[tix] = g_startM[tix]; sh_end[tix] = g_endM[tix]; }
    }
    __syncwarp();

    const int b = blockIdx.x * 32 + threadIdx.x;
    const float4* e4  = (const float4*)(em + (size_t)b * TT * K);
    const int*   trow = tags + (size_t)b * TT;

    // Sequence length = popcount of this row's prefix mask.
    int len = 0;
    if (g_u8mode) {
        const uint4* m4 = (const uint4*)((const unsigned char*)maskp + (size_t)b * TT);
        unsigned acc = 0u;
#pragma unroll
        for (int i = 0; i < TT / 16; i++) {
            uint4 x = m4[i];
            acc = __dp4a(x.x, 0x01010101u, acc);
            acc = __dp4a(x.y, 0x01010101u, acc);
            acc = __dp4a(x.z, 0x01010101u, acc);
            acc = __dp4a(x.w, 0x01010101u, acc);
        }
        len = (int)acc;
    } else {
        const uint4* m4 = (const uint4*)((const unsigned*)maskp + (size_t)b * TT);
        for (int i = 0; i < TT / 4; i++) {
            uint4 x = m4[i];
            len += (x.x != 0u) + (x.y != 0u) + (x.z != 0u) + (x.w != 0u);
        }
    }

    // Sparse transition coefficients (26 registers).
    const float cA0 = g_A[0], cA1 = g_A[1], cA2 = g_A[2], cA3 = g_A[3];
    const float cA4 = g_A[4], cA5 = g_A[5], cA6 = g_A[6], cA7 = g_A[7];
    const float cA8 = g_A[8], cA9 = g_A[9], cA10 = g_A[10];
    const float cC0 = g_C[0], cC1 = g_C[1], cC2 = g_C[2], cC3 = g_C[3], cC4 = g_C[4];
    const float cD0 = g_D[0], cD1 = g_D[1], cD2 = g_D[2], cD3 = g_D[3], cD4 = g_D[4];
    const float cF0 = g_F[0], cF1 = g_F[1], cF2 = g_F[2], cF3 = g_F[3], cF4 = g_F[4];

    // Triple-buffered chunk windows (prefetch distance ~8 steps).
    float4 QA[11], QB[11], QC[11];
    int4 TA, TBv, TCv;
    LOADC(QA, TA, 0)
    LOADC(QB, TBv, 1)
    LOADC(QC, TCv, 2)

    float r0, r1, r2, r3, r4, r5, r6, r7, r8, r9, r10, A0, score;
    int ptag;
    {
        // t = 0 (start), then steps 1..3 of chunk 0.
        float e0_ = GETF(QA, 0), e1_ = GETF(QA, 1), e2_ = GETF(QA, 2);
        float e3_ = GETF(QA, 3), e4_ = GETF(QA, 4), e5_ = GETF(QA, 5);
        float e6_ = GETF(QA, 6), e7_ = GETF(QA, 7), e8_ = GETF(QA, 8);
        float e9_ = GETF(QA, 9), e10_ = GETF(QA, 10);
        float aO_ = sh_start[0] + e0_;
        A0 = aO_;
        r0 = 1.0f;
        r1  = __expf(sh_start[1]  + e1_  - aO_);
        r2  = __expf(sh_start[2]  + e2_  - aO_);   // start -10000 -> exactly 0
        r3  = __expf(sh_start[3]  + e3_  - aO_);
        r4  = __expf(sh_start[4]  + e4_  - aO_);
        r5  = __expf(sh_start[5]  + e5_  - aO_);
        r6  = __expf(sh_start[6]  + e6_  - aO_);
        r7  = __expf(sh_start[7]  + e7_  - aO_);
        r8  = __expf(sh_start[8]  + e8_  - aO_);
        r9  = __expf(sh_start[9]  + e9_  - aO_);
        r10 = __expf(sh_start[10] + e10_ - aO_);
        ptag  = TA.x;
        score = sh_start[ptag] + PICK(ptag);
        STEP(QA, TA, 0, 1)
        STEP(QA, TA, 0, 2)
        STEP(QA, TA, 0, 3)
        RENORM
    }

    // Chunks 1..127: 42 rotations of 3 + final chunk.
    int c = 1;
#pragma unroll 1
    for (int it = 0; it < 42; it++) {
        LOADC(QA, TA, c + 2)  PROC(QB, TBv, c)
        LOADC(QB, TBv, c + 3) PROC(QC, TCv, c + 1)
        LOADC(QC, TCv, c + 4) PROC(QA, TA, c + 2)
        c += 3;
    }
    PROC(QB, TBv, 127)   // c == 127; QB holds chunk 127

    // z = A0 + log( sum_j rho_j * exp(end_j) )
    float v0 = fmaf(r1, __expf(sh_end[1]), r0 * __expf(sh_end[0]));
    float v1 = fmaf(r3, __expf(sh_end[3]), r2 * __expf(sh_end[2]));
    float v2 = fmaf(r5, __expf(sh_end[5]), r4 * __expf(sh_end[4]));
    float v3 = fmaf(r7, __expf(sh_end[7]), r6 * __expf(sh_end[6]));
    float v4 = fmaf(r9, __expf(sh_end[9]), r8 * __expf(sh_end[8]));
    float v5 = r10 * __expf(sh_end[10]);
    float z = A0 + __logf(((v0 + v1) + (v2 + v3)) + (v4 + v5));

    score += sh_end[ptag];
    float nll = (score - z) * (1.0f / (float)BB);

#pragma unroll
    for (int k = 16; k; k >>= 1) nll += __shfl_xor_sync(0xFFFFFFFFu, nll, k);
    if (threadIdx.x == 0) atomicAdd(out, nll);
}

extern "C" void kernel_launch(void* const* d_in, const int* in_sizes, int n_in,
                              void* d_out, int out_size) {
    const float* em     = (const float*)d_in[0];
    const void*  maskp  = d_in[1];
    const int*   tags   = (const int*)d_in[2];
    const float* trans  = (const float*)d_in[3];
    const float* startv = (const float*)d_in[4];
    const float* endv   = (const float*)d_in[5];
    float* out = (float*)d_out;

    setup_kernel<<<1, 128>>>(trans, startv, endv, maskp, out);
    crf_kernel<<<BB / 32, 32>>>(em, maskp, tags, out);
}